// round 8
// baseline (speedup 1.0000x reference)
#include <cuda_runtime.h>
#include <cstdint>
#include <math.h>

#define K_DIM   1024
#define S_LEN   2048
#define BATCH   2
#define NHEADS  16
#define HDIM    64
#define BH      (BATCH*NHEADS)

// GEMM tiling
#define TILE_M  128
#define TILE_N  128
#define TILE_K  32
#define LDS_ROW 36
#define STG_F   (128*LDS_ROW)
#define STG_B   (STG_F*4)
#define GEMM_DSMEM (4*STG_B)

// Attention tiling
#define AQT 128
#define AKT 64
#define ANT (S_LEN/AKT)            // 32 key tiles
// smem float offsets
#define A_QP  0                    // [128][68] Q then P
#define A_KS  8704                 // [2][64][68]
#define A_VS  17408                // [2][64][72]
#define A_MK  26624                // [2][64]
#define ATTN_DSMEM ((26624 + 128) * 4)   // 107008 B

// Scratch (device globals: no allocation allowed)
__device__ float g_q[BH * S_LEN * HDIM];
__device__ float g_k[BH * S_LEN * HDIM];
__device__ float g_v[BH * S_LEN * HDIM];
__device__ float g_attn[BATCH * S_LEN * K_DIM];
__device__ float g_xc[BATCH * S_LEN * K_DIM];
__device__ float g_wq[3 * K_DIM * K_DIM];
__device__ float g_wo[K_DIM * K_DIM];

// ---------------------------------------------------------------------------
__device__ __forceinline__ uint32_t s2u(const void* p) {
    uint32_t a;
    asm("{ .reg .u64 t; cvta.to.shared.u64 t, %1; cvt.u32.u64 %0, t; }" : "=r"(a) : "l"(p));
    return a;
}
#define CP16(dst, src) \
    asm volatile("cp.async.cg.shared.global [%0], [%1], 16;" :: "r"(dst), "l"(src) : "memory")
#define CP_COMMIT() asm volatile("cp.async.commit_group;" ::: "memory")
#define CP_WAIT1()  asm volatile("cp.async.wait_group 1;" ::: "memory")
#define CP_WAIT0()  asm volatile("cp.async.wait_group 0;" ::: "memory")

#define MMA_TF32(c, a, b) \
    asm volatile("mma.sync.aligned.m16n8k8.row.col.f32.tf32.tf32.f32 " \
        "{%0,%1,%2,%3}, {%4,%5,%6,%7}, {%8,%9}, {%0,%1,%2,%3};" \
        : "+f"((c)[0]), "+f"((c)[1]), "+f"((c)[2]), "+f"((c)[3]) \
        : "r"((a)[0]), "r"((a)[1]), "r"((a)[2]), "r"((a)[3]), \
          "r"((b)[0]), "r"((b)[1]))

__device__ __forceinline__ float tf32r(float v) {
    uint32_t r; asm("cvt.rna.tf32.f32 %0, %1;" : "=r"(r) : "f"(v));
    return __uint_as_float(r);
}
__global__ void cvt_tf32_kernel(const float4* __restrict__ in, float4* __restrict__ out, int n4) {
    int i = blockIdx.x * 256 + threadIdx.x;
    if (i < n4) {
        float4 v = in[i];
        v.x = tf32r(v.x); v.y = tf32r(v.y); v.z = tf32r(v.z); v.w = tf32r(v.w);
        out[i] = v;
    }
}

// ---------------------------------------------------------------------------
// Tensor-core NT GEMM (validated in round 6). mode 1 now tf32-rounds its
// outputs so attention's mma consumes round-to-nearest operands.
// ---------------------------------------------------------------------------
__global__ __launch_bounds__(256, 1) void gemm_mma_kernel(
    const float* __restrict__ A, const float* __restrict__ W,
    const float* __restrict__ bias, float* __restrict__ C,
    int N, int mode)
{
    extern __shared__ float sf[];
    float* sA = sf;
    float* sB = sf + 2 * STG_F;

    const int tid  = threadIdx.x;
    const int wid  = tid >> 5;
    const int lane = tid & 31;
    const int wm = wid >> 1;
    const int wn = wid & 1;
    const int gq = lane >> 2;
    const int gt = lane & 3;
    const int mbase = blockIdx.y * TILE_M;
    const int nbase = blockIdx.x * TILE_N;

    const uint32_t sa_u = s2u(sA);
    const uint32_t sb_u = s2u(sB);

    const float* pa[4]; const float* pb[4]; uint32_t da[4], db[4];
#pragma unroll
    for (int i = 0; i < 4; i++) {
        int slot = i * 256 + tid;
        int row = slot >> 3;
        int c   = slot & 7;
        pa[i] = A + (size_t)(mbase + row) * K_DIM + c * 4;
        pb[i] = W + (size_t)(nbase + row) * K_DIM + c * 4;
        da[i] = sa_u + row * (LDS_ROW * 4) + c * 16;
        db[i] = sb_u + row * (LDS_ROW * 4) + c * 16;
    }

#define LOAD_STAGE(st, kc) do {                                   \
        uint32_t so = (uint32_t)(st) * STG_B;                     \
        int ko = (kc) * TILE_K;                                   \
        _Pragma("unroll")                                         \
        for (int i = 0; i < 4; i++) {                             \
            CP16(da[i] + so, pa[i] + ko);                         \
            CP16(db[i] + so, pb[i] + ko);                         \
        }                                                         \
        CP_COMMIT();                                              \
    } while (0)

    float acc[2][8][4];
#pragma unroll
    for (int mt = 0; mt < 2; mt++)
#pragma unroll
        for (int nt = 0; nt < 8; nt++)
#pragma unroll
            for (int r = 0; r < 4; r++) acc[mt][nt][r] = 0.f;

    LOAD_STAGE(0, 0);

    const int NCH = K_DIM / TILE_K;
    for (int kc = 0; kc < NCH; kc++) {
        if (kc + 1 < NCH) { LOAD_STAGE((kc + 1) & 1, kc + 1); CP_WAIT1(); }
        else              { CP_WAIT0(); }
        __syncthreads();

        const float* Ab = sA + (kc & 1) * STG_F;
        const float* Bb = sB + (kc & 1) * STG_F;

#pragma unroll
        for (int k8 = 0; k8 < TILE_K; k8 += 8) {
            uint32_t a[2][4], b[8][2];
#pragma unroll
            for (int mt = 0; mt < 2; mt++) {
                int r0 = wm * 32 + mt * 16 + gq;
                a[mt][0] = __float_as_uint(Ab[r0 * LDS_ROW + k8 + gt]);
                a[mt][1] = __float_as_uint(Ab[(r0 + 8) * LDS_ROW + k8 + gt]);
                a[mt][2] = __float_as_uint(Ab[r0 * LDS_ROW + k8 + 4 + gt]);
                a[mt][3] = __float_as_uint(Ab[(r0 + 8) * LDS_ROW + k8 + 4 + gt]);
            }
#pragma unroll
            for (int nt = 0; nt < 8; nt++) {
                int cn = wn * 64 + nt * 8 + gq;
                b[nt][0] = __float_as_uint(Bb[cn * LDS_ROW + k8 + gt]);
                b[nt][1] = __float_as_uint(Bb[cn * LDS_ROW + k8 + 4 + gt]);
            }
#pragma unroll
            for (int mt = 0; mt < 2; mt++)
#pragma unroll
                for (int nt = 0; nt < 8; nt++)
                    MMA_TF32(acc[mt][nt], a[mt], b[nt]);
        }
        __syncthreads();
    }

#pragma unroll
    for (int mt = 0; mt < 2; mt++) {
#pragma unroll
        for (int nt = 0; nt < 8; nt++) {
            int m0 = mbase + wm * 32 + mt * 16 + gq;
            int n0 = nbase + wn * 64 + nt * 8 + 2 * gt;
            float b0 = bias[n0], b1 = bias[n0 + 1];
            float v0 = acc[mt][nt][0] + b0, v1 = acc[mt][nt][1] + b1;
            float v2 = acc[mt][nt][2] + b0, v3 = acc[mt][nt][3] + b1;
            if (mode == 0) {
                *(float2*)&C[(size_t)m0 * N + n0]       = make_float2(v0, v1);
                *(float2*)&C[(size_t)(m0 + 8) * N + n0] = make_float2(v2, v3);
            } else {
                int part = n0 >> 10, nn = n0 & 1023;
                int h = nn >> 6, d = nn & 63;
                float* buf = (part == 0) ? g_q : (part == 1) ? g_k : g_v;
                int b_ = m0 >> 11, s0 = m0 & 2047;
                size_t base = (((size_t)(b_ * NHEADS + h)) * S_LEN);
                *(float2*)&buf[(base + s0) * HDIM + d] =
                    make_float2(tf32r(v0), tf32r(v1));
                *(float2*)&buf[(base + s0 + 8) * HDIM + d] =
                    make_float2(tf32r(v2), tf32r(v3));
            }
        }
    }
}

// ---------------------------------------------------------------------------
// Flash ALiBi attention via mma.sync tf32.
// CTA: 256 thr / 8 warps, Q-tile 128 rows (16/warp), key tiles of 64,
// double-buffered cp.async K/V. Q fragments register-resident.
// P routed through per-warp-private smem (syncwarp only).
// ---------------------------------------------------------------------------
__global__ __launch_bounds__(256, 1) void attn_mma_kernel(const unsigned int* __restrict__ mask)
{
    extern __shared__ float sm[];
    float* QP = sm + A_QP;          // [128][68]
    float* KS = sm + A_KS;          // [2][64][68]
    float* VS = sm + A_VS;          // [2][64][72]
    float* MK = sm + A_MK;          // [2][64]

    const int tid = threadIdx.x;
    const int wid = tid >> 5;
    const int lane = tid & 31;
    const int gq = lane >> 2;
    const int gt = lane & 3;
    const int bh = blockIdx.y;
    const int b  = bh >> 4;
    const int h  = bh & 15;
    const int qbase = blockIdx.x * AQT;

    const float slope = exp2f(-0.5f * (float)(h + 1));
    const float scale = 0.125f;

    const float* qptr = g_q + (size_t)bh * S_LEN * HDIM;
    const float* kptr = g_k + (size_t)bh * S_LEN * HDIM;
    const float* vptr = g_v + (size_t)bh * S_LEN * HDIM;
    const unsigned int* mrow = mask + (size_t)b * S_LEN;

    const uint32_t ks_u = s2u(KS);
    const uint32_t vs_u = s2u(VS);

    // Load Q tile coalesced into smem
#pragma unroll
    for (int r = 0; r < 8; r++) {
        int idx = tid + 256 * r;
        int row = idx >> 4;
        int c4  = (idx & 15) * 4;
        *(float4*)&QP[row * 68 + c4] = *(const float4*)&qptr[(qbase + row) * HDIM + c4];
    }
    __syncthreads();

    // Extract Q fragments (row.major A for m16n8k8): reused across all key tiles
    const int r0 = wid * 16 + gq;           // warp-local row (and +8)
    uint32_t qf[8][4];
#pragma unroll
    for (int ki = 0; ki < 8; ki++) {
        int k = ki * 8;
        qf[ki][0] = __float_as_uint(QP[r0 * 68 + k + gt]);
        qf[ki][1] = __float_as_uint(QP[(r0 + 8) * 68 + k + gt]);
        qf[ki][2] = __float_as_uint(QP[r0 * 68 + k + 4 + gt]);
        qf[ki][3] = __float_as_uint(QP[(r0 + 8) * 68 + k + 4 + gt]);
    }
    __syncthreads();    // QP now repurposed as P buffer

    float m0 = -1e30f, m1 = -1e30f, l0 = 0.f, l1 = 0.f;
    float oacc[8][4];
#pragma unroll
    for (int nt = 0; nt < 8; nt++)
#pragma unroll
        for (int r = 0; r < 4; r++) oacc[nt][r] = 0.f;

#define LOADKV(st, kt_) do {                                                   \
        int kb_ = (kt_) * AKT;                                                 \
        uint32_t ko_ = ks_u + (uint32_t)(st) * (4352 * 4);                     \
        uint32_t vo_ = vs_u + (uint32_t)(st) * (4608 * 4);                     \
        _Pragma("unroll")                                                      \
        for (int i = 0; i < 4; i++) {                                          \
            int idx = tid + 256 * i;                                           \
            int row = idx >> 4;                                                \
            int c   = idx & 15;                                                \
            CP16(ko_ + (uint32_t)(row * 68 + c * 4) * 4,                       \
                 kptr + (size_t)(kb_ + row) * HDIM + c * 4);                   \
            CP16(vo_ + (uint32_t)(row * 72 + c * 4) * 4,                       \
                 vptr + (size_t)(kb_ + row) * HDIM + c * 4);                   \
        }                                                                      \
        CP_COMMIT();                                                           \
        if (tid < 64) MK[(st) * 64 + tid] = (mrow[kb_ + tid] != 0u) ? 0.f : -1e30f; \
    } while (0)

    LOADKV(0, 0);

    const float rowf0 = (float)(qbase + r0);
    const float rowf1 = (float)(qbase + r0 + 8);

    for (int kt = 0; kt < ANT; kt++) {
        if (kt + 1 < ANT) { LOADKV((kt + 1) & 1, kt + 1); CP_WAIT1(); }
        else              { CP_WAIT0(); }
        __syncthreads();

        const float* Kb = KS + (kt & 1) * 4352;
        const float* Vb = VS + (kt & 1) * 4608;
        const float* Mb = MK + (kt & 1) * 64;
        const int kbase = kt * AKT;

        // GEMM1: S = Q K^T  (warp 16 x 64)
        float sacc[8][4];
#pragma unroll
        for (int nt = 0; nt < 8; nt++)
#pragma unroll
            for (int r = 0; r < 4; r++) sacc[nt][r] = 0.f;
#pragma unroll
        for (int ki = 0; ki < 8; ki++) {
            int k = ki * 8;
            uint32_t bb[8][2];
#pragma unroll
            for (int nt = 0; nt < 8; nt++) {
                bb[nt][0] = __float_as_uint(Kb[(nt * 8 + gq) * 68 + k + gt]);
                bb[nt][1] = __float_as_uint(Kb[(nt * 8 + gq) * 68 + k + 4 + gt]);
            }
#pragma unroll
            for (int nt = 0; nt < 8; nt++)
                MMA_TF32(sacc[nt], qf[ki], bb[nt]);
        }

        // Bias + mask + online softmax (rows r0 via c0/c1, r0+8 via c2/c3)
        float rm0 = -1e30f, rm1 = -1e30f;
#pragma unroll
        for (int nt = 0; nt < 8; nt++) {
#pragma unroll
            for (int e = 0; e < 2; e++) {
                int cl = nt * 8 + 2 * gt + e;
                float colf = (float)(kbase + cl);
                float mk = Mb[cl];
                float v0 = sacc[nt][e]     * scale - slope * fabsf(colf - rowf0) + mk;
                float v1 = sacc[nt][2 + e] * scale - slope * fabsf(colf - rowf1) + mk;
                sacc[nt][e] = v0; sacc[nt][2 + e] = v1;
                rm0 = fmaxf(rm0, v0); rm1 = fmaxf(rm1, v1);
            }
        }
        rm0 = fmaxf(rm0, __shfl_xor_sync(0xffffffffu, rm0, 1));
        rm0 = fmaxf(rm0, __shfl_xor_sync(0xffffffffu, rm0, 2));
        rm1 = fmaxf(rm1, __shfl_xor_sync(0xffffffffu, rm1, 1));
        rm1 = fmaxf(rm1, __shfl_xor_sync(0xffffffffu, rm1, 2));

        float mn0 = fmaxf(m0, rm0), mn1 = fmaxf(m1, rm1);
        float al0 = __expf(m0 - mn0), al1 = __expf(m1 - mn1);
        float rs0 = 0.f, rs1 = 0.f;
#pragma unroll
        for (int nt = 0; nt < 8; nt++) {
#pragma unroll
            for (int e = 0; e < 2; e++) {
                float p0 = __expf(sacc[nt][e] - mn0);
                float p1 = __expf(sacc[nt][2 + e] - mn1);
                sacc[nt][e] = p0; sacc[nt][2 + e] = p1;
                rs0 += p0; rs1 += p1;
            }
        }
        rs0 += __shfl_xor_sync(0xffffffffu, rs0, 1);
        rs0 += __shfl_xor_sync(0xffffffffu, rs0, 2);
        rs1 += __shfl_xor_sync(0xffffffffu, rs1, 1);
        rs1 += __shfl_xor_sync(0xffffffffu, rs1, 2);
        l0 = l0 * al0 + rs0; l1 = l1 * al1 + rs1;
        m0 = mn0; m1 = mn1;
#pragma unroll
        for (int nt = 0; nt < 8; nt++) {
            oacc[nt][0] *= al0; oacc[nt][1] *= al0;
            oacc[nt][2] *= al1; oacc[nt][3] *= al1;
        }

        // Stash P (tf32-rounded) in per-warp-private smem region
        __syncwarp();
#pragma unroll
        for (int nt = 0; nt < 8; nt++) {
            *(float2*)&QP[r0 * 68 + nt * 8 + 2 * gt] =
                make_float2(tf32r(sacc[nt][0]), tf32r(sacc[nt][1]));
            *(float2*)&QP[(r0 + 8) * 68 + nt * 8 + 2 * gt] =
                make_float2(tf32r(sacc[nt][2]), tf32r(sacc[nt][3]));
        }
        __syncwarp();

        // GEMM2: O += P V  (K dim = 64 keys)
#pragma unroll
        for (int ki = 0; ki < 8; ki++) {
            int k = ki * 8;
            uint32_t a[4];
            a[0] = __float_as_uint(QP[r0 * 68 + k + gt]);
            a[1] = __float_as_uint(QP[(r0 + 8) * 68 + k + gt]);
            a[2] = __float_as_uint(QP[r0 * 68 + k + 4 + gt]);
            a[3] = __float_as_uint(QP[(r0 + 8) * 68 + k + 4 + gt]);
            uint32_t bb[8][2];
#pragma unroll
            for (int nt = 0; nt < 8; nt++) {
                bb[nt][0] = __float_as_uint(Vb[(k + gt) * 72 + nt * 8 + gq]);
                bb[nt][1] = __float_as_uint(Vb[(k + 4 + gt) * 72 + nt * 8 + gq]);
            }
#pragma unroll
            for (int nt = 0; nt < 8; nt++)
                MMA_TF32(oacc[nt], a, bb[nt]);
        }
        __syncthreads();   // protect K/V double buffers
    }

    // Epilogue: rows qbase+r0 and +8, cols h*64 + nt*8 + 2*gt
    float inv0 = 1.f / l0, inv1 = 1.f / l1;
    size_t orow0 = ((size_t)b * S_LEN + qbase + r0) * K_DIM + h * HDIM;
    size_t orow1 = orow0 + 8 * K_DIM;
#pragma unroll
    for (int nt = 0; nt < 8; nt++) {
        int c = nt * 8 + 2 * gt;
        *(float2*)&g_attn[orow0 + c] =
            make_float2(tf32r(oacc[nt][0] * inv0), tf32r(oacc[nt][1] * inv0));
        *(float2*)&g_attn[orow1 + c] =
            make_float2(tf32r(oacc[nt][2] * inv1), tf32r(oacc[nt][3] * inv1));
    }
}

// ---------------------------------------------------------------------------
extern "C" void kernel_launch(void* const* d_in, const int* in_sizes, int n_in,
                              void* d_out, int out_size)
{
    const float* x      = (const float*)d_in[0];
    const unsigned int* mask = (const unsigned int*)d_in[1];
    const float* qkv_w  = (const float*)d_in[2];
    const float* qkv_b  = (const float*)d_in[3];
    const float* out_w  = (const float*)d_in[4];
    const float* out_b  = (const float*)d_in[5];
    float* out = (float*)d_out;

    void *p_attn, *p_xc, *p_wq, *p_wo;
    cudaGetSymbolAddress(&p_attn, g_attn);
    cudaGetSymbolAddress(&p_xc, g_xc);
    cudaGetSymbolAddress(&p_wq, g_wq);
    cudaGetSymbolAddress(&p_wo, g_wo);

    cudaFuncSetAttribute(attn_mma_kernel, cudaFuncAttributeMaxDynamicSharedMemorySize, ATTN_DSMEM);
    cudaFuncSetAttribute(gemm_mma_kernel, cudaFuncAttributeMaxDynamicSharedMemorySize, GEMM_DSMEM);

    // 0) tf32-round inputs
    {
        int n4 = BATCH * S_LEN * K_DIM / 4;
        cvt_tf32_kernel<<<(n4 + 255) / 256, 256>>>((const float4*)x, (float4*)p_xc, n4);
        n4 = 3 * K_DIM * K_DIM / 4;
        cvt_tf32_kernel<<<(n4 + 255) / 256, 256>>>((const float4*)qkv_w, (float4*)p_wq, n4);
        n4 = K_DIM * K_DIM / 4;
        cvt_tf32_kernel<<<(n4 + 255) / 256, 256>>>((const float4*)out_w, (float4*)p_wo, n4);
    }

    // 1) QKV projection [4096 x 3072]
    dim3 g1(3 * K_DIM / TILE_N, BATCH * S_LEN / TILE_M);
    gemm_mma_kernel<<<g1, 256, GEMM_DSMEM>>>((const float*)p_xc, (const float*)p_wq,
                                             qkv_b, nullptr, 3 * K_DIM, 1);

    // 2) Attention (mma.sync)
    dim3 g2(S_LEN / AQT, BH);
    attn_mma_kernel<<<g2, 256, ATTN_DSMEM>>>(mask);

    // 3) Output projection [4096 x 1024]
    dim3 g3(K_DIM / TILE_N, BATCH * S_LEN / TILE_M);
    gemm_mma_kernel<<<g3, 256, GEMM_DSMEM>>>((const float*)p_attn, (const float*)p_wo,
                                             out_b, out, K_DIM, 0);
}

// round 9
// speedup vs baseline: 1.0018x; 1.0018x over previous
#include <cuda_runtime.h>
#include <cstdint>
#include <math.h>

#define K_DIM   1024
#define S_LEN   2048
#define BATCH   2
#define NHEADS  16
#define HDIM    64
#define BH      (BATCH*NHEADS)

// GEMM tiling
#define TILE_M  128
#define TILE_N  128
#define TILE_K  32
#define LDS_ROW 36
#define STG_F   (128*LDS_ROW)
#define STG_B   (STG_F*4)
#define GEMM_DSMEM (4*STG_B)

// Attention tiling
#define AQT 128
#define AKT 64
#define ANT (S_LEN/AKT)            // 32 key tiles
// smem float offsets
#define A_QP  0                    // [128][68] Q then P
#define A_KS  8704                 // [2][64][68]
#define A_VS  17408                // [2][64][72]
#define A_MK  26624                // [2][64]
#define ATTN_DSMEM ((26624 + 128) * 4)   // 107008 B

// Scratch (device globals: no allocation allowed)
__device__ float g_q[BH * S_LEN * HDIM];
__device__ float g_k[BH * S_LEN * HDIM];
__device__ float g_v[BH * S_LEN * HDIM];
__device__ float g_attn[BATCH * S_LEN * K_DIM];
__device__ float g_xc[BATCH * S_LEN * K_DIM];
__device__ float g_wq[3 * K_DIM * K_DIM];
__device__ float g_wo[K_DIM * K_DIM];

// ---------------------------------------------------------------------------
__device__ __forceinline__ uint32_t s2u(const void* p) {
    uint32_t a;
    asm("{ .reg .u64 t; cvta.to.shared.u64 t, %1; cvt.u32.u64 %0, t; }" : "=r"(a) : "l"(p));
    return a;
}
#define CP16(dst, src) \
    asm volatile("cp.async.cg.shared.global [%0], [%1], 16;" :: "r"(dst), "l"(src) : "memory")
#define CP_COMMIT() asm volatile("cp.async.commit_group;" ::: "memory")
#define CP_WAIT1()  asm volatile("cp.async.wait_group 1;" ::: "memory")
#define CP_WAIT0()  asm volatile("cp.async.wait_group 0;" ::: "memory")

#define MMA_TF32(c, a, b) \
    asm volatile("mma.sync.aligned.m16n8k8.row.col.f32.tf32.tf32.f32 " \
        "{%0,%1,%2,%3}, {%4,%5,%6,%7}, {%8,%9}, {%0,%1,%2,%3};" \
        : "+f"((c)[0]), "+f"((c)[1]), "+f"((c)[2]), "+f"((c)[3]) \
        : "r"((a)[0]), "r"((a)[1]), "r"((a)[2]), "r"((a)[3]), \
          "r"((b)[0]), "r"((b)[1]))

__device__ __forceinline__ float tf32r(float v) {
    uint32_t r; asm("cvt.rna.tf32.f32 %0, %1;" : "=r"(r) : "f"(v));
    return __uint_as_float(r);
}
__global__ void cvt_tf32_kernel(const float4* __restrict__ in, float4* __restrict__ out, int n4) {
    int i = blockIdx.x * 256 + threadIdx.x;
    if (i < n4) {
        float4 v = in[i];
        v.x = tf32r(v.x); v.y = tf32r(v.y); v.z = tf32r(v.z); v.w = tf32r(v.w);
        out[i] = v;
    }
}

// ---------------------------------------------------------------------------
// Tensor-core NT GEMM (validated in round 6). mode 1 now tf32-rounds its
// outputs so attention's mma consumes round-to-nearest operands.
// ---------------------------------------------------------------------------
__global__ __launch_bounds__(256, 1) void gemm_mma_kernel(
    const float* __restrict__ A, const float* __restrict__ W,
    const float* __restrict__ bias, float* __restrict__ C,
    int N, int mode)
{
    extern __shared__ float sf[];
    float* sA = sf;
    float* sB = sf + 2 * STG_F;

    const int tid  = threadIdx.x;
    const int wid  = tid >> 5;
    const int lane = tid & 31;
    const int wm = wid >> 1;
    const int wn = wid & 1;
    const int gq = lane >> 2;
    const int gt = lane & 3;
    const int mbase = blockIdx.y * TILE_M;
    const int nbase = blockIdx.x * TILE_N;

    const uint32_t sa_u = s2u(sA);
    const uint32_t sb_u = s2u(sB);

    const float* pa[4]; const float* pb[4]; uint32_t da[4], db[4];
#pragma unroll
    for (int i = 0; i < 4; i++) {
        int slot = i * 256 + tid;
        int row = slot >> 3;
        int c   = slot & 7;
        pa[i] = A + (size_t)(mbase + row) * K_DIM + c * 4;
        pb[i] = W + (size_t)(nbase + row) * K_DIM + c * 4;
        da[i] = sa_u + row * (LDS_ROW * 4) + c * 16;
        db[i] = sb_u + row * (LDS_ROW * 4) + c * 16;
    }

#define LOAD_STAGE(st, kc) do {                                   \
        uint32_t so = (uint32_t)(st) * STG_B;                     \
        int ko = (kc) * TILE_K;                                   \
        _Pragma("unroll")                                         \
        for (int i = 0; i < 4; i++) {                             \
            CP16(da[i] + so, pa[i] + ko);                         \
            CP16(db[i] + so, pb[i] + ko);                         \
        }                                                         \
        CP_COMMIT();                                              \
    } while (0)

    float acc[2][8][4];
#pragma unroll
    for (int mt = 0; mt < 2; mt++)
#pragma unroll
        for (int nt = 0; nt < 8; nt++)
#pragma unroll
            for (int r = 0; r < 4; r++) acc[mt][nt][r] = 0.f;

    LOAD_STAGE(0, 0);

    const int NCH = K_DIM / TILE_K;
    for (int kc = 0; kc < NCH; kc++) {
        if (kc + 1 < NCH) { LOAD_STAGE((kc + 1) & 1, kc + 1); CP_WAIT1(); }
        else              { CP_WAIT0(); }
        __syncthreads();

        const float* Ab = sA + (kc & 1) * STG_F;
        const float* Bb = sB + (kc & 1) * STG_F;

#pragma unroll
        for (int k8 = 0; k8 < TILE_K; k8 += 8) {
            uint32_t a[2][4], b[8][2];
#pragma unroll
            for (int mt = 0; mt < 2; mt++) {
                int r0 = wm * 32 + mt * 16 + gq;
                a[mt][0] = __float_as_uint(Ab[r0 * LDS_ROW + k8 + gt]);
                a[mt][1] = __float_as_uint(Ab[(r0 + 8) * LDS_ROW + k8 + gt]);
                a[mt][2] = __float_as_uint(Ab[r0 * LDS_ROW + k8 + 4 + gt]);
                a[mt][3] = __float_as_uint(Ab[(r0 + 8) * LDS_ROW + k8 + 4 + gt]);
            }
#pragma unroll
            for (int nt = 0; nt < 8; nt++) {
                int cn = wn * 64 + nt * 8 + gq;
                b[nt][0] = __float_as_uint(Bb[cn * LDS_ROW + k8 + gt]);
                b[nt][1] = __float_as_uint(Bb[cn * LDS_ROW + k8 + 4 + gt]);
            }
#pragma unroll
            for (int mt = 0; mt < 2; mt++)
#pragma unroll
                for (int nt = 0; nt < 8; nt++)
                    MMA_TF32(acc[mt][nt], a[mt], b[nt]);
        }
        __syncthreads();
    }

#pragma unroll
    for (int mt = 0; mt < 2; mt++) {
#pragma unroll
        for (int nt = 0; nt < 8; nt++) {
            int m0 = mbase + wm * 32 + mt * 16 + gq;
            int n0 = nbase + wn * 64 + nt * 8 + 2 * gt;
            float b0 = bias[n0], b1 = bias[n0 + 1];
            float v0 = acc[mt][nt][0] + b0, v1 = acc[mt][nt][1] + b1;
            float v2 = acc[mt][nt][2] + b0, v3 = acc[mt][nt][3] + b1;
            if (mode == 0) {
                *(float2*)&C[(size_t)m0 * N + n0]       = make_float2(v0, v1);
                *(float2*)&C[(size_t)(m0 + 8) * N + n0] = make_float2(v2, v3);
            } else {
                int part = n0 >> 10, nn = n0 & 1023;
                int h = nn >> 6, d = nn & 63;
                float* buf = (part == 0) ? g_q : (part == 1) ? g_k : g_v;
                int b_ = m0 >> 11, s0 = m0 & 2047;
                size_t base = (((size_t)(b_ * NHEADS + h)) * S_LEN);
                *(float2*)&buf[(base + s0) * HDIM + d] =
                    make_float2(tf32r(v0), tf32r(v1));
                *(float2*)&buf[(base + s0 + 8) * HDIM + d] =
                    make_float2(tf32r(v2), tf32r(v3));
            }
        }
    }
}

// ---------------------------------------------------------------------------
// Flash ALiBi attention via mma.sync tf32.
// CTA: 256 thr / 8 warps, Q-tile 128 rows (16/warp), key tiles of 64,
// double-buffered cp.async K/V. Q fragments register-resident.
// P routed through per-warp-private smem (syncwarp only).
// ---------------------------------------------------------------------------
__global__ __launch_bounds__(256, 1) void attn_mma_kernel(const unsigned int* __restrict__ mask)
{
    extern __shared__ float sm[];
    float* QP = sm + A_QP;          // [128][68]
    float* KS = sm + A_KS;          // [2][64][68]
    float* VS = sm + A_VS;          // [2][64][72]
    float* MK = sm + A_MK;          // [2][64]

    const int tid = threadIdx.x;
    const int wid = tid >> 5;
    const int lane = tid & 31;
    const int gq = lane >> 2;
    const int gt = lane & 3;
    const int bh = blockIdx.y;
    const int b  = bh >> 4;
    const int h  = bh & 15;
    const int qbase = blockIdx.x * AQT;

    const float slope = exp2f(-0.5f * (float)(h + 1));
    const float scale = 0.125f;

    const float* qptr = g_q + (size_t)bh * S_LEN * HDIM;
    const float* kptr = g_k + (size_t)bh * S_LEN * HDIM;
    const float* vptr = g_v + (size_t)bh * S_LEN * HDIM;
    const unsigned int* mrow = mask + (size_t)b * S_LEN;

    const uint32_t ks_u = s2u(KS);
    const uint32_t vs_u = s2u(VS);

    // Load Q tile coalesced into smem
#pragma unroll
    for (int r = 0; r < 8; r++) {
        int idx = tid + 256 * r;
        int row = idx >> 4;
        int c4  = (idx & 15) * 4;
        *(float4*)&QP[row * 68 + c4] = *(const float4*)&qptr[(qbase + row) * HDIM + c4];
    }
    __syncthreads();

    // Extract Q fragments (row.major A for m16n8k8): reused across all key tiles
    const int r0 = wid * 16 + gq;           // warp-local row (and +8)
    uint32_t qf[8][4];
#pragma unroll
    for (int ki = 0; ki < 8; ki++) {
        int k = ki * 8;
        qf[ki][0] = __float_as_uint(QP[r0 * 68 + k + gt]);
        qf[ki][1] = __float_as_uint(QP[(r0 + 8) * 68 + k + gt]);
        qf[ki][2] = __float_as_uint(QP[r0 * 68 + k + 4 + gt]);
        qf[ki][3] = __float_as_uint(QP[(r0 + 8) * 68 + k + 4 + gt]);
    }
    __syncthreads();    // QP now repurposed as P buffer

    float m0 = -1e30f, m1 = -1e30f, l0 = 0.f, l1 = 0.f;
    float oacc[8][4];
#pragma unroll
    for (int nt = 0; nt < 8; nt++)
#pragma unroll
        for (int r = 0; r < 4; r++) oacc[nt][r] = 0.f;

#define LOADKV(st, kt_) do {                                                   \
        int kb_ = (kt_) * AKT;                                                 \
        uint32_t ko_ = ks_u + (uint32_t)(st) * (4352 * 4);                     \
        uint32_t vo_ = vs_u + (uint32_t)(st) * (4608 * 4);                     \
        _Pragma("unroll")                                                      \
        for (int i = 0; i < 4; i++) {                                          \
            int idx = tid + 256 * i;                                           \
            int row = idx >> 4;                                                \
            int c   = idx & 15;                                                \
            CP16(ko_ + (uint32_t)(row * 68 + c * 4) * 4,                       \
                 kptr + (size_t)(kb_ + row) * HDIM + c * 4);                   \
            CP16(vo_ + (uint32_t)(row * 72 + c * 4) * 4,                       \
                 vptr + (size_t)(kb_ + row) * HDIM + c * 4);                   \
        }                                                                      \
        CP_COMMIT();                                                           \
        if (tid < 64) MK[(st) * 64 + tid] = (mrow[kb_ + tid] != 0u) ? 0.f : -1e30f; \
    } while (0)

    LOADKV(0, 0);

    const float rowf0 = (float)(qbase + r0);
    const float rowf1 = (float)(qbase + r0 + 8);

    for (int kt = 0; kt < ANT; kt++) {
        if (kt + 1 < ANT) { LOADKV((kt + 1) & 1, kt + 1); CP_WAIT1(); }
        else              { CP_WAIT0(); }
        __syncthreads();

        const float* Kb = KS + (kt & 1) * 4352;
        const float* Vb = VS + (kt & 1) * 4608;
        const float* Mb = MK + (kt & 1) * 64;
        const int kbase = kt * AKT;

        // GEMM1: S = Q K^T  (warp 16 x 64)
        float sacc[8][4];
#pragma unroll
        for (int nt = 0; nt < 8; nt++)
#pragma unroll
            for (int r = 0; r < 4; r++) sacc[nt][r] = 0.f;
#pragma unroll
        for (int ki = 0; ki < 8; ki++) {
            int k = ki * 8;
            uint32_t bb[8][2];
#pragma unroll
            for (int nt = 0; nt < 8; nt++) {
                bb[nt][0] = __float_as_uint(Kb[(nt * 8 + gq) * 68 + k + gt]);
                bb[nt][1] = __float_as_uint(Kb[(nt * 8 + gq) * 68 + k + 4 + gt]);
            }
#pragma unroll
            for (int nt = 0; nt < 8; nt++)
                MMA_TF32(sacc[nt], qf[ki], bb[nt]);
        }

        // Bias + mask + online softmax (rows r0 via c0/c1, r0+8 via c2/c3)
        float rm0 = -1e30f, rm1 = -1e30f;
#pragma unroll
        for (int nt = 0; nt < 8; nt++) {
#pragma unroll
            for (int e = 0; e < 2; e++) {
                int cl = nt * 8 + 2 * gt + e;
                float colf = (float)(kbase + cl);
                float mk = Mb[cl];
                float v0 = sacc[nt][e]     * scale - slope * fabsf(colf - rowf0) + mk;
                float v1 = sacc[nt][2 + e] * scale - slope * fabsf(colf - rowf1) + mk;
                sacc[nt][e] = v0; sacc[nt][2 + e] = v1;
                rm0 = fmaxf(rm0, v0); rm1 = fmaxf(rm1, v1);
            }
        }
        rm0 = fmaxf(rm0, __shfl_xor_sync(0xffffffffu, rm0, 1));
        rm0 = fmaxf(rm0, __shfl_xor_sync(0xffffffffu, rm0, 2));
        rm1 = fmaxf(rm1, __shfl_xor_sync(0xffffffffu, rm1, 1));
        rm1 = fmaxf(rm1, __shfl_xor_sync(0xffffffffu, rm1, 2));

        float mn0 = fmaxf(m0, rm0), mn1 = fmaxf(m1, rm1);
        float al0 = __expf(m0 - mn0), al1 = __expf(m1 - mn1);
        float rs0 = 0.f, rs1 = 0.f;
#pragma unroll
        for (int nt = 0; nt < 8; nt++) {
#pragma unroll
            for (int e = 0; e < 2; e++) {
                float p0 = __expf(sacc[nt][e] - mn0);
                float p1 = __expf(sacc[nt][2 + e] - mn1);
                sacc[nt][e] = p0; sacc[nt][2 + e] = p1;
                rs0 += p0; rs1 += p1;
            }
        }
        rs0 += __shfl_xor_sync(0xffffffffu, rs0, 1);
        rs0 += __shfl_xor_sync(0xffffffffu, rs0, 2);
        rs1 += __shfl_xor_sync(0xffffffffu, rs1, 1);
        rs1 += __shfl_xor_sync(0xffffffffu, rs1, 2);
        l0 = l0 * al0 + rs0; l1 = l1 * al1 + rs1;
        m0 = mn0; m1 = mn1;
#pragma unroll
        for (int nt = 0; nt < 8; nt++) {
            oacc[nt][0] *= al0; oacc[nt][1] *= al0;
            oacc[nt][2] *= al1; oacc[nt][3] *= al1;
        }

        // Stash P (tf32-rounded) in per-warp-private smem region
        __syncwarp();
#pragma unroll
        for (int nt = 0; nt < 8; nt++) {
            *(float2*)&QP[r0 * 68 + nt * 8 + 2 * gt] =
                make_float2(tf32r(sacc[nt][0]), tf32r(sacc[nt][1]));
            *(float2*)&QP[(r0 + 8) * 68 + nt * 8 + 2 * gt] =
                make_float2(tf32r(sacc[nt][2]), tf32r(sacc[nt][3]));
        }
        __syncwarp();

        // GEMM2: O += P V  (K dim = 64 keys)
#pragma unroll
        for (int ki = 0; ki < 8; ki++) {
            int k = ki * 8;
            uint32_t a[4];
            a[0] = __float_as_uint(QP[r0 * 68 + k + gt]);
            a[1] = __float_as_uint(QP[(r0 + 8) * 68 + k + gt]);
            a[2] = __float_as_uint(QP[r0 * 68 + k + 4 + gt]);
            a[3] = __float_as_uint(QP[(r0 + 8) * 68 + k + 4 + gt]);
            uint32_t bb[8][2];
#pragma unroll
            for (int nt = 0; nt < 8; nt++) {
                bb[nt][0] = __float_as_uint(Vb[(k + gt) * 72 + nt * 8 + gq]);
                bb[nt][1] = __float_as_uint(Vb[(k + 4 + gt) * 72 + nt * 8 + gq]);
            }
#pragma unroll
            for (int nt = 0; nt < 8; nt++)
                MMA_TF32(oacc[nt], a, bb[nt]);
        }
        __syncthreads();   // protect K/V double buffers
    }

    // Epilogue: rows qbase+r0 and +8, cols h*64 + nt*8 + 2*gt
    float inv0 = 1.f / l0, inv1 = 1.f / l1;
    size_t orow0 = ((size_t)b * S_LEN + qbase + r0) * K_DIM + h * HDIM;
    size_t orow1 = orow0 + 8 * K_DIM;
#pragma unroll
    for (int nt = 0; nt < 8; nt++) {
        int c = nt * 8 + 2 * gt;
        *(float2*)&g_attn[orow0 + c] =
            make_float2(tf32r(oacc[nt][0] * inv0), tf32r(oacc[nt][1] * inv0));
        *(float2*)&g_attn[orow1 + c] =
            make_float2(tf32r(oacc[nt][2] * inv1), tf32r(oacc[nt][3] * inv1));
    }
}

// ---------------------------------------------------------------------------
extern "C" void kernel_launch(void* const* d_in, const int* in_sizes, int n_in,
                              void* d_out, int out_size)
{
    const float* x      = (const float*)d_in[0];
    const unsigned int* mask = (const unsigned int*)d_in[1];
    const float* qkv_w  = (const float*)d_in[2];
    const float* qkv_b  = (const float*)d_in[3];
    const float* out_w  = (const float*)d_in[4];
    const float* out_b  = (const float*)d_in[5];
    float* out = (float*)d_out;

    void *p_attn, *p_xc, *p_wq, *p_wo;
    cudaGetSymbolAddress(&p_attn, g_attn);
    cudaGetSymbolAddress(&p_xc, g_xc);
    cudaGetSymbolAddress(&p_wq, g_wq);
    cudaGetSymbolAddress(&p_wo, g_wo);

    cudaFuncSetAttribute(attn_mma_kernel, cudaFuncAttributeMaxDynamicSharedMemorySize, ATTN_DSMEM);
    cudaFuncSetAttribute(gemm_mma_kernel, cudaFuncAttributeMaxDynamicSharedMemorySize, GEMM_DSMEM);

    // 0) tf32-round inputs
    {
        int n4 = BATCH * S_LEN * K_DIM / 4;
        cvt_tf32_kernel<<<(n4 + 255) / 256, 256>>>((const float4*)x, (float4*)p_xc, n4);
        n4 = 3 * K_DIM * K_DIM / 4;
        cvt_tf32_kernel<<<(n4 + 255) / 256, 256>>>((const float4*)qkv_w, (float4*)p_wq, n4);
        n4 = K_DIM * K_DIM / 4;
        cvt_tf32_kernel<<<(n4 + 255) / 256, 256>>>((const float4*)out_w, (float4*)p_wo, n4);
    }

    // 1) QKV projection [4096 x 3072]
    dim3 g1(3 * K_DIM / TILE_N, BATCH * S_LEN / TILE_M);
    gemm_mma_kernel<<<g1, 256, GEMM_DSMEM>>>((const float*)p_xc, (const float*)p_wq,
                                             qkv_b, nullptr, 3 * K_DIM, 1);

    // 2) Attention (mma.sync)
    dim3 g2(S_LEN / AQT, BH);
    attn_mma_kernel<<<g2, 256, ATTN_DSMEM>>>(mask);

    // 3) Output projection [4096 x 1024]
    dim3 g3(K_DIM / TILE_N, BATCH * S_LEN / TILE_M);
    gemm_mma_kernel<<<g3, 256, GEMM_DSMEM>>>((const float*)p_attn, (const float*)p_wo,
                                             out_b, out, K_DIM, 0);
}